// round 14
// baseline (speedup 1.0000x reference)
#include <cuda_runtime.h>
#include <cuda_fp16.h>
#include <cuda_bf16.h>
#include <cstdint>

#define N_NODES 100000
#define N_EDGES 1600000
#define IN_F    64
#define N_CLS   64

// Scratch: g = feat @ W^T in fp16 (12.8 MB -> L2-resident), CSR offsets
__device__ __half g_buf[(size_t)N_NODES * N_CLS];
__device__ int    g_row_start[N_NODES + 1];

#define NB_ROW  ((N_EDGES / 4 + 255) / 256)   /* rowptr blocks */
#define NB_GEMM ((N_NODES + 63) / 64)         /* gemm blocks   */

// ---------------------------------------------------------------------------
// packed f32x2 helpers (fma.rn.f32x2 is never emitted by ptxas from C++)
// ---------------------------------------------------------------------------
__device__ __forceinline__ unsigned long long fma2(unsigned long long a,
                                                   unsigned long long b,
                                                   unsigned long long c) {
    unsigned long long d;
    asm("fma.rn.f32x2 %0, %1, %2, %3;" : "=l"(d) : "l"(a), "l"(b), "l"(c));
    return d;
}
__device__ __forceinline__ unsigned long long packff(float x, float y) {
    unsigned long long d;
    asm("mov.b64 %0, {%1, %2};" : "=l"(d) : "f"(x), "f"(y));
    return d;
}
__device__ __forceinline__ void unpack2(unsigned long long v, float& lo, float& hi) {
    asm("mov.b64 {%0, %1}, %2;" : "=f"(lo), "=f"(hi) : "l"(v));
}
// half2 bits -> packed f32x2 (b64)
__device__ __forceinline__ unsigned long long h2_to_f32x2(unsigned h2) {
    unsigned long long d;
    asm("{\n\t"
        ".reg .b16 l, h;\n\t"
        ".reg .f32 fl, fh;\n\t"
        "mov.b32 {l, h}, %1;\n\t"
        "cvt.f32.f16 fl, l;\n\t"
        "cvt.f32.f16 fh, h;\n\t"
        "mov.b64 %0, {fl, fh};\n\t"
        "}" : "=l"(d) : "r"(h2));
    return d;
}

// ---------------------------------------------------------------------------
// tf32 mma helpers
// ---------------------------------------------------------------------------
__device__ __forceinline__ unsigned f2tf32(float x) {
    unsigned u;
    asm("cvt.rna.tf32.f32 %0, %1;" : "=r"(u) : "f"(x));
    return u;
}
__device__ __forceinline__ void mma_tf32(float& c0, float& c1, float& c2, float& c3,
                                         unsigned a0, unsigned a1, unsigned a2, unsigned a3,
                                         unsigned b0, unsigned b1) {
    asm("mma.sync.aligned.m16n8k8.row.col.f32.tf32.tf32.f32 "
        "{%0,%1,%2,%3}, {%4,%5,%6,%7}, {%8,%9}, {%0,%1,%2,%3};"
        : "+f"(c0), "+f"(c1), "+f"(c2), "+f"(c3)
        : "r"(a0), "r"(a1), "r"(a2), "r"(a3), "r"(b0), "r"(b1));
}

// ---------------------------------------------------------------------------
// Fused prep kernel: blocks [0, NB_ROW) build row_start (transition scan),
// blocks [NB_ROW, ...) compute g = half(feat @ W^T) via tf32 mma.
// ---------------------------------------------------------------------------
#define SM_PAD 68
__global__ __launch_bounds__(256) void prep_kernel(const int* __restrict__ edge_row,
                                                   int* __restrict__ row_start,
                                                   const float* __restrict__ feat,
                                                   const float* __restrict__ W,
                                                   __half* __restrict__ g) {
    __shared__ float sA[64 * SM_PAD];
    __shared__ float sB[64 * SM_PAD];

    if (blockIdx.x < NB_ROW) {
        int t = blockIdx.x * blockDim.x + threadIdx.x;
        if (t >= N_EDGES / 4) return;
        int4 r4 = ((const int4*)edge_row)[t];
        int e0 = t * 4;
        int prev = (t == 0) ? -1 : __ldg(&edge_row[e0 - 1]);

        for (int q = prev + 1; q <= r4.x; ++q) row_start[q] = e0;
        for (int q = r4.x + 1; q <= r4.y; ++q) row_start[q] = e0 + 1;
        for (int q = r4.y + 1; q <= r4.z; ++q) row_start[q] = e0 + 2;
        for (int q = r4.z + 1; q <= r4.w; ++q) row_start[q] = e0 + 3;

        if (e0 + 4 == N_EDGES)
            for (int q = r4.w + 1; q <= N_NODES; ++q) row_start[q] = N_EDGES;
        return;
    }

    // ---- GEMM tile 64x64, 8 warps (4x2) ----
    int tid  = threadIdx.x;
    int lane = tid & 31;
    int warp = tid >> 5;
    int row0 = (blockIdx.x - NB_ROW) * 64;
    int maxrow = N_NODES - row0;

    for (int idx = tid; idx < 64 * 16; idx += 256) {
        int n = idx >> 4, q = idx & 15;
        float4 v = ((const float4*)W)[idx];
        float* dst = &sB[n * SM_PAD + q * 4];
        dst[0] = v.x; dst[1] = v.y; dst[2] = v.z; dst[3] = v.w;
    }
    for (int idx = tid; idx < 64 * 16; idx += 256) {
        int r = idx >> 4, q = idx & 15;
        float4 v = (r < maxrow) ? __ldcs(&((const float4*)(feat + (size_t)row0 * 64))[idx])
                                : make_float4(0.f, 0.f, 0.f, 0.f);
        float* dst = &sA[r * SM_PAD + q * 4];
        dst[0] = v.x; dst[1] = v.y; dst[2] = v.z; dst[3] = v.w;
    }
    __syncthreads();

    int g4 = lane >> 2;
    int t4 = lane & 3;
    int warp_m = warp >> 1;
    int warp_n = warp & 1;

    float acc[4][4];
    #pragma unroll
    for (int i = 0; i < 4; ++i)
        #pragma unroll
        for (int j = 0; j < 4; ++j) acc[i][j] = 0.f;

    int ra = warp_m * 16 + g4;

    #pragma unroll
    for (int ks = 0; ks < 8; ++ks) {
        int k0 = ks * 8;
        unsigned a0 = f2tf32(sA[ra * SM_PAD + k0 + t4]);
        unsigned a1 = f2tf32(sA[(ra + 8) * SM_PAD + k0 + t4]);
        unsigned a2 = f2tf32(sA[ra * SM_PAD + k0 + t4 + 4]);
        unsigned a3 = f2tf32(sA[(ra + 8) * SM_PAD + k0 + t4 + 4]);
        #pragma unroll
        for (int nt = 0; nt < 4; ++nt) {
            int n = (warp_n * 4 + nt) * 8 + g4;
            unsigned b0 = f2tf32(sB[n * SM_PAD + k0 + t4]);
            unsigned b1 = f2tf32(sB[n * SM_PAD + k0 + t4 + 4]);
            mma_tf32(acc[nt][0], acc[nt][1], acc[nt][2], acc[nt][3],
                     a0, a1, a2, a3, b0, b1);
        }
    }

    #pragma unroll
    for (int nt = 0; nt < 4; ++nt) {
        int col = (warp_n * 4 + nt) * 8 + 2 * t4;
        if (ra < maxrow) {
            __half2 h = __floats2half2_rn(acc[nt][0], acc[nt][1]);
            *(__half2*)(g + (size_t)(row0 + ra) * 64 + col) = h;
        }
        if (ra + 8 < maxrow) {
            __half2 h = __floats2half2_rn(acc[nt][2], acc[nt][3]);
            *(__half2*)(g + (size_t)(row0 + ra + 8) * 64 + col) = h;
        }
    }
}

// ---------------------------------------------------------------------------
// SpMM: one warp per node, 8 lanes per edge (slot=lane>>3, sub=lane&7).
// FULL 2-DEEP PIPELINE over 8-edge blocks:
//   scalars (col,val) fetched 2 blocks ahead, gathers 1 block ahead,
//   FMAs consume the current block. The col->gather dependency spans two
//   iterations of FMA work, so steady-state is issue-bound, not latency-bound.
// ---------------------------------------------------------------------------
__global__ __launch_bounds__(256) void spmm_kernel(const int* __restrict__ row_start,
                                                   const int* __restrict__ edge_col,
                                                   const float* __restrict__ edge_val,
                                                   const __half* __restrict__ g,
                                                   const float* __restrict__ b,
                                                   float* __restrict__ out) {
    int w = (blockIdx.x * blockDim.x + threadIdx.x) >> 5;
    int lane = threadIdx.x & 31;
    if (w >= N_NODES) return;

    int slot = lane >> 3;   // which of 4 concurrent edges
    int sub  = lane & 7;    // which 16B chunk of the 128B row

    int s = __ldg(&row_start[w]);
    int e = __ldg(&row_start[w + 1]);

    const char* gbase = (const char*)g + sub * 16;

    unsigned long long acc0 = 0ull, acc1 = 0ull, acc2 = 0ull, acc3 = 0ull;

    int i = s;                       // current block
    bool have  = (i + 8 <= e);       // block i valid
    int i2 = i + 8;
    bool have2 = (i2 + 8 <= e);      // block i2 valid

    // stage regs: current block (scalars + gathers), next block (scalars)
    int   ca = 0, cb = 0;  float va = 0.f, vb = 0.f;
    uint4 A = make_uint4(0u,0u,0u,0u), B = make_uint4(0u,0u,0u,0u);
    int   nca = 0, ncb = 0; float nva = 0.f, nvb = 0.f;

    if (have) {
        ca = __ldg(&edge_col[i + slot]);
        va = __ldg(&edge_val[i + slot]);
        cb = __ldg(&edge_col[i + 4 + slot]);
        vb = __ldg(&edge_val[i + 4 + slot]);
        A = *(const uint4*)(gbase + (size_t)ca * 128);
        B = *(const uint4*)(gbase + (size_t)cb * 128);
    }
    if (have2) {
        nca = __ldg(&edge_col[i2 + slot]);
        nva = __ldg(&edge_val[i2 + slot]);
        ncb = __ldg(&edge_col[i2 + 4 + slot]);
        nvb = __ldg(&edge_val[i2 + 4 + slot]);
    }

    while (have) {
        // issue next block's gathers (cols already resident)
        uint4 nA = make_uint4(0u,0u,0u,0u), nB = make_uint4(0u,0u,0u,0u);
        if (have2) {
            nA = *(const uint4*)(gbase + (size_t)nca * 128);
            nB = *(const uint4*)(gbase + (size_t)ncb * 128);
        }
        // issue block-after-next's scalars
        int i3 = i2 + 8;
        bool have3 = (i3 + 8 <= e);
        int mca = 0, mcb = 0; float mva = 0.f, mvb = 0.f;
        if (have3) {
            mca = __ldg(&edge_col[i3 + slot]);
            mva = __ldg(&edge_val[i3 + slot]);
            mcb = __ldg(&edge_col[i3 + 4 + slot]);
            mvb = __ldg(&edge_val[i3 + 4 + slot]);
        }
        // consume current block
        unsigned long long vva = packff(va, va);
        unsigned long long vvb = packff(vb, vb);
        acc0 = fma2(h2_to_f32x2(A.x), vva, acc0);
        acc1 = fma2(h2_to_f32x2(A.y), vva, acc1);
        acc2 = fma2(h2_to_f32x2(A.z), vva, acc2);
        acc3 = fma2(h2_to_f32x2(A.w), vva, acc3);
        acc0 = fma2(h2_to_f32x2(B.x), vvb, acc0);
        acc1 = fma2(h2_to_f32x2(B.y), vvb, acc1);
        acc2 = fma2(h2_to_f32x2(B.z), vvb, acc2);
        acc3 = fma2(h2_to_f32x2(B.w), vvb, acc3);
        // rotate pipeline
        A = nA; B = nB; va = nva; vb = nvb;
        nca = mca; ncb = mcb; nva = mva; nvb = mvb;
        i = i2; i2 = i3; have = have2; have2 = have3;
    }

    // tail: <8 edges remain; 4 per step, invalid slots contribute v=0
    for (; i < e; i += 4) {
        int  m = i + slot;
        bool p = (m < e);
        int  mm = p ? m : i;
        int   c = __ldg(&edge_col[mm]);
        float v = p ? __ldg(&edge_val[mm]) : 0.f;
        uint4 T = *(const uint4*)(gbase + (size_t)c * 128);
        unsigned long long vv = packff(v, v);
        acc0 = fma2(h2_to_f32x2(T.x), vv, acc0);
        acc1 = fma2(h2_to_f32x2(T.y), vv, acc1);
        acc2 = fma2(h2_to_f32x2(T.z), vv, acc2);
        acc3 = fma2(h2_to_f32x2(T.w), vv, acc3);
    }

    float r0, r1, r2, r3, r4, r5, r6, r7;
    unpack2(acc0, r0, r1);
    unpack2(acc1, r2, r3);
    unpack2(acc2, r4, r5);
    unpack2(acc3, r6, r7);

    // reduce the 4 slots
    r0 += __shfl_xor_sync(0xffffffffu, r0, 8);
    r1 += __shfl_xor_sync(0xffffffffu, r1, 8);
    r2 += __shfl_xor_sync(0xffffffffu, r2, 8);
    r3 += __shfl_xor_sync(0xffffffffu, r3, 8);
    r4 += __shfl_xor_sync(0xffffffffu, r4, 8);
    r5 += __shfl_xor_sync(0xffffffffu, r5, 8);
    r6 += __shfl_xor_sync(0xffffffffu, r6, 8);
    r7 += __shfl_xor_sync(0xffffffffu, r7, 8);
    r0 += __shfl_xor_sync(0xffffffffu, r0, 16);
    r1 += __shfl_xor_sync(0xffffffffu, r1, 16);
    r2 += __shfl_xor_sync(0xffffffffu, r2, 16);
    r3 += __shfl_xor_sync(0xffffffffu, r3, 16);
    r4 += __shfl_xor_sync(0xffffffffu, r4, 16);
    r5 += __shfl_xor_sync(0xffffffffu, r5, 16);
    r6 += __shfl_xor_sync(0xffffffffu, r6, 16);
    r7 += __shfl_xor_sync(0xffffffffu, r7, 16);

    if (lane < 8) {
        float4 b0 = ((const float4*)b)[lane * 2];
        float4 b1 = ((const float4*)b)[lane * 2 + 1];
        float4 o0 = make_float4(r0 + b0.x, r1 + b0.y, r2 + b0.z, r3 + b0.w);
        float4 o1 = make_float4(r4 + b1.x, r5 + b1.y, r6 + b1.z, r7 + b1.w);
        float4* op = (float4*)(out + (size_t)w * 64 + lane * 8);
        __stcs(&op[0], o0);
        __stcs(&op[1], o1);
    }
}

// ---------------------------------------------------------------------------
extern "C" void kernel_launch(void* const* d_in, const int* in_sizes, int n_in,
                              void* d_out, int out_size) {
    const float* feat     = (const float*)d_in[0];
    const int*   edge_row = (const int*)  d_in[1];
    const int*   edge_col = (const int*)  d_in[2];
    const float* edge_val = (const float*)d_in[3];
    const float* W        = (const float*)d_in[4];
    const float* b        = (const float*)d_in[5];
    float*       out      = (float*)d_out;

    __half* g;
    int*    row_start;
    cudaGetSymbolAddress((void**)&g, g_buf);
    cudaGetSymbolAddress((void**)&row_start, g_row_start);

    // 1) fused: rowptr scan + g = half(feat @ W^T)
    prep_kernel<<<NB_ROW + NB_GEMM, 256>>>(edge_row, row_start, feat, W, g);

    // 2) out = A @ g + b   (one warp per node, 2-deep pipelined gathers)
    int total_threads = N_NODES * 32;
    spmm_kernel<<<(total_threads + 255) / 256, 256>>>(row_start, edge_col, edge_val,
                                                      g, b, out);
}

// round 17
// speedup vs baseline: 1.0839x; 1.0839x over previous
#include <cuda_runtime.h>
#include <cuda_fp16.h>
#include <cuda_bf16.h>
#include <cstdint>

#define N_NODES 100000
#define N_EDGES 1600000
#define IN_F    64
#define N_CLS   64

// Scratch: g = feat @ W^T in fp16 (12.8 MB, L2-resident), CSR offsets,
// packed (col,val) edge stream (8B/edge).
__device__ __half              g_buf[(size_t)N_NODES * N_CLS];
__device__ int                 g_row_start[N_NODES + 1];
__device__ unsigned long long  ev_buf[N_EDGES];

#define NB_ROW  ((N_EDGES / 4 + 255) / 256)   /* rowptr blocks: 1563 */
#define NB_PACK ((N_EDGES / 4 + 255) / 256)   /* pack blocks:   1563 */
#define NB_GEMM ((N_NODES + 63) / 64)         /* gemm blocks:   1563 */

// ---------------------------------------------------------------------------
// packed f32x2 helpers (fma.rn.f32x2 is never emitted by ptxas from C++)
// ---------------------------------------------------------------------------
__device__ __forceinline__ unsigned long long fma2(unsigned long long a,
                                                   unsigned long long b,
                                                   unsigned long long c) {
    unsigned long long d;
    asm("fma.rn.f32x2 %0, %1, %2, %3;" : "=l"(d) : "l"(a), "l"(b), "l"(c));
    return d;
}
__device__ __forceinline__ unsigned long long packff(float x, float y) {
    unsigned long long d;
    asm("mov.b64 %0, {%1, %2};" : "=l"(d) : "f"(x), "f"(y));
    return d;
}
__device__ __forceinline__ void unpack2(unsigned long long v, float& lo, float& hi) {
    asm("mov.b64 {%0, %1}, %2;" : "=f"(lo), "=f"(hi) : "l"(v));
}
// half2 bits -> packed f32x2 (b64)
__device__ __forceinline__ unsigned long long h2_to_f32x2(unsigned h2) {
    unsigned long long d;
    asm("{\n\t"
        ".reg .b16 l, h;\n\t"
        ".reg .f32 fl, fh;\n\t"
        "mov.b32 {l, h}, %1;\n\t"
        "cvt.f32.f16 fl, l;\n\t"
        "cvt.f32.f16 fh, h;\n\t"
        "mov.b64 %0, {fl, fh};\n\t"
        "}" : "=l"(d) : "r"(h2));
    return d;
}

// ---------------------------------------------------------------------------
// tf32 mma helpers
// ---------------------------------------------------------------------------
__device__ __forceinline__ unsigned f2tf32(float x) {
    unsigned u;
    asm("cvt.rna.tf32.f32 %0, %1;" : "=r"(u) : "f"(x));
    return u;
}
__device__ __forceinline__ void mma_tf32(float& c0, float& c1, float& c2, float& c3,
                                         unsigned a0, unsigned a1, unsigned a2, unsigned a3,
                                         unsigned b0, unsigned b1) {
    asm("mma.sync.aligned.m16n8k8.row.col.f32.tf32.tf32.f32 "
        "{%0,%1,%2,%3}, {%4,%5,%6,%7}, {%8,%9}, {%0,%1,%2,%3};"
        : "+f"(c0), "+f"(c1), "+f"(c2), "+f"(c3)
        : "r"(a0), "r"(a1), "r"(a2), "r"(a3), "r"(b0), "r"(b1));
}

// ---------------------------------------------------------------------------
// Fused prep kernel:
//   blocks [0, NB_ROW)                      : row_start transition scan
//   blocks [NB_ROW, NB_ROW+NB_PACK)         : pack ev[i] = (col[i], val[i])
//   blocks [NB_ROW+NB_PACK, ...)            : g = half(feat @ W^T), tf32 mma
// ---------------------------------------------------------------------------
#define SM_PAD 68
__global__ __launch_bounds__(256) void prep_kernel(const int* __restrict__ edge_row,
                                                   int* __restrict__ row_start,
                                                   const int* __restrict__ edge_col,
                                                   const float* __restrict__ edge_val,
                                                   unsigned long long* __restrict__ ev,
                                                   const float* __restrict__ feat,
                                                   const float* __restrict__ W,
                                                   __half* __restrict__ g) {
    __shared__ float sA[64 * SM_PAD];
    __shared__ float sB[64 * SM_PAD];

    if (blockIdx.x < NB_ROW) {
        // ---- rowptr transition scan (4 edges/thread) ----
        int t = blockIdx.x * blockDim.x + threadIdx.x;
        if (t >= N_EDGES / 4) return;
        int4 r4 = ((const int4*)edge_row)[t];
        int e0 = t * 4;
        int prev = (t == 0) ? -1 : __ldg(&edge_row[e0 - 1]);

        for (int q = prev + 1; q <= r4.x; ++q) row_start[q] = e0;
        for (int q = r4.x + 1; q <= r4.y; ++q) row_start[q] = e0 + 1;
        for (int q = r4.y + 1; q <= r4.z; ++q) row_start[q] = e0 + 2;
        for (int q = r4.z + 1; q <= r4.w; ++q) row_start[q] = e0 + 3;

        if (e0 + 4 == N_EDGES)
            for (int q = r4.w + 1; q <= N_NODES; ++q) row_start[q] = N_EDGES;
        return;
    }

    if (blockIdx.x < NB_ROW + NB_PACK) {
        // ---- pack (col,val) -> ev, 4 edges/thread, 16B stores ----
        int t = (blockIdx.x - NB_ROW) * blockDim.x + threadIdx.x;
        if (t >= N_EDGES / 4) return;
        int4   c4 = __ldcs(&((const int4*)edge_col)[t]);
        float4 v4 = __ldcs(&((const float4*)edge_val)[t]);
        unsigned long long p0 = (unsigned long long)(unsigned)c4.x |
                                ((unsigned long long)__float_as_uint(v4.x) << 32);
        unsigned long long p1 = (unsigned long long)(unsigned)c4.y |
                                ((unsigned long long)__float_as_uint(v4.y) << 32);
        unsigned long long p2 = (unsigned long long)(unsigned)c4.z |
                                ((unsigned long long)__float_as_uint(v4.z) << 32);
        unsigned long long p3 = (unsigned long long)(unsigned)c4.w |
                                ((unsigned long long)__float_as_uint(v4.w) << 32);
        longlong2* dst = (longlong2*)(ev + (size_t)t * 4);
        dst[0] = make_longlong2((long long)p0, (long long)p1);
        dst[1] = make_longlong2((long long)p2, (long long)p3);
        return;
    }

    // ---- GEMM tile 64x64, 8 warps (4x2) ----
    int tid  = threadIdx.x;
    int lane = tid & 31;
    int warp = tid >> 5;
    int row0 = (blockIdx.x - NB_ROW - NB_PACK) * 64;
    int maxrow = N_NODES - row0;

    for (int idx = tid; idx < 64 * 16; idx += 256) {
        int n = idx >> 4, q = idx & 15;
        float4 v = ((const float4*)W)[idx];
        float* dst = &sB[n * SM_PAD + q * 4];
        dst[0] = v.x; dst[1] = v.y; dst[2] = v.z; dst[3] = v.w;
    }
    for (int idx = tid; idx < 64 * 16; idx += 256) {
        int r = idx >> 4, q = idx & 15;
        float4 v = (r < maxrow) ? __ldcs(&((const float4*)(feat + (size_t)row0 * 64))[idx])
                                : make_float4(0.f, 0.f, 0.f, 0.f);
        float* dst = &sA[r * SM_PAD + q * 4];
        dst[0] = v.x; dst[1] = v.y; dst[2] = v.z; dst[3] = v.w;
    }
    __syncthreads();

    int g4 = lane >> 2;
    int t4 = lane & 3;
    int warp_m = warp >> 1;
    int warp_n = warp & 1;

    float acc[4][4];
    #pragma unroll
    for (int i = 0; i < 4; ++i)
        #pragma unroll
        for (int j = 0; j < 4; ++j) acc[i][j] = 0.f;

    int ra = warp_m * 16 + g4;

    #pragma unroll
    for (int ks = 0; ks < 8; ++ks) {
        int k0 = ks * 8;
        unsigned a0 = f2tf32(sA[ra * SM_PAD + k0 + t4]);
        unsigned a1 = f2tf32(sA[(ra + 8) * SM_PAD + k0 + t4]);
        unsigned a2 = f2tf32(sA[ra * SM_PAD + k0 + t4 + 4]);
        unsigned a3 = f2tf32(sA[(ra + 8) * SM_PAD + k0 + t4 + 4]);
        #pragma unroll
        for (int nt = 0; nt < 4; ++nt) {
            int n = (warp_n * 4 + nt) * 8 + g4;
            unsigned b0 = f2tf32(sB[n * SM_PAD + k0 + t4]);
            unsigned b1 = f2tf32(sB[n * SM_PAD + k0 + t4 + 4]);
            mma_tf32(acc[nt][0], acc[nt][1], acc[nt][2], acc[nt][3],
                     a0, a1, a2, a3, b0, b1);
        }
    }

    #pragma unroll
    for (int nt = 0; nt < 4; ++nt) {
        int col = (warp_n * 4 + nt) * 8 + 2 * t4;
        if (ra < maxrow) {
            __half2 h = __floats2half2_rn(acc[nt][0], acc[nt][1]);
            *(__half2*)(g + (size_t)(row0 + ra) * 64 + col) = h;
        }
        if (ra + 8 < maxrow) {
            __half2 h = __floats2half2_rn(acc[nt][2], acc[nt][3]);
            *(__half2*)(g + (size_t)(row0 + ra + 8) * 64 + col) = h;
        }
    }
}

// ---------------------------------------------------------------------------
// SpMM: one warp per node, 8 lanes per edge (slot=lane>>3, sub=lane&7).
// 16 edges per iteration: 4 LDG.64 packed (col,val) + 4 LDG.128 gathers per
// lane, so a deg~16 row is ONE iteration (2 latency humps per warp total).
// Math: fma.rn.f32x2, fp32 accumulation.
// ---------------------------------------------------------------------------
__global__ __launch_bounds__(256) void spmm_kernel(const int* __restrict__ row_start,
                                                   const unsigned long long* __restrict__ ev,
                                                   const __half* __restrict__ g,
                                                   const float* __restrict__ b,
                                                   float* __restrict__ out) {
    int w = (blockIdx.x * blockDim.x + threadIdx.x) >> 5;
    int lane = threadIdx.x & 31;
    if (w >= N_NODES) return;

    int slot = lane >> 3;   // which of 4 concurrent edges in a group
    int sub  = lane & 7;    // which 16B chunk of the 128B row

    int s = __ldg(&row_start[w]);
    int e = __ldg(&row_start[w + 1]);

    const char* gbase = (const char*)g + sub * 16;

    unsigned long long acc0 = 0ull, acc1 = 0ull, acc2 = 0ull, acc3 = 0ull;

    int i = s;
    // main: 16 edges per iteration (4 groups of 4); all scalars then all
    // gathers issue back-to-back -> 2 latency humps per iteration.
    for (; i + 16 <= e; i += 16) {
        unsigned long long p0 = __ldg(&ev[i + slot]);
        unsigned long long p1 = __ldg(&ev[i + 4 + slot]);
        unsigned long long p2 = __ldg(&ev[i + 8 + slot]);
        unsigned long long p3 = __ldg(&ev[i + 12 + slot]);
        int2 q0 = *(int2*)&p0;  int2 q1 = *(int2*)&p1;
        int2 q2 = *(int2*)&p2;  int2 q3 = *(int2*)&p3;
        uint4 A0 = *(const uint4*)(gbase + (size_t)(unsigned)q0.x * 128);
        uint4 A1 = *(const uint4*)(gbase + (size_t)(unsigned)q1.x * 128);
        uint4 A2 = *(const uint4*)(gbase + (size_t)(unsigned)q2.x * 128);
        uint4 A3 = *(const uint4*)(gbase + (size_t)(unsigned)q3.x * 128);
        float v0 = __int_as_float(q0.y);
        float v1 = __int_as_float(q1.y);
        float v2 = __int_as_float(q2.y);
        float v3 = __int_as_float(q3.y);
        unsigned long long vv0 = packff(v0, v0);
        unsigned long long vv1 = packff(v1, v1);
        unsigned long long vv2 = packff(v2, v2);
        unsigned long long vv3 = packff(v3, v3);
        acc0 = fma2(h2_to_f32x2(A0.x), vv0, acc0);
        acc1 = fma2(h2_to_f32x2(A0.y), vv0, acc1);
        acc2 = fma2(h2_to_f32x2(A0.z), vv0, acc2);
        acc3 = fma2(h2_to_f32x2(A0.w), vv0, acc3);
        acc0 = fma2(h2_to_f32x2(A1.x), vv1, acc0);
        acc1 = fma2(h2_to_f32x2(A1.y), vv1, acc1);
        acc2 = fma2(h2_to_f32x2(A1.z), vv1, acc2);
        acc3 = fma2(h2_to_f32x2(A1.w), vv1, acc3);
        acc0 = fma2(h2_to_f32x2(A2.x), vv2, acc0);
        acc1 = fma2(h2_to_f32x2(A2.y), vv2, acc1);
        acc2 = fma2(h2_to_f32x2(A2.z), vv2, acc2);
        acc3 = fma2(h2_to_f32x2(A2.w), vv2, acc3);
        acc0 = fma2(h2_to_f32x2(A3.x), vv3, acc0);
        acc1 = fma2(h2_to_f32x2(A3.y), vv3, acc1);
        acc2 = fma2(h2_to_f32x2(A3.z), vv3, acc2);
        acc3 = fma2(h2_to_f32x2(A3.w), vv3, acc3);
    }
    // tail: 4 edges per step, invalid slots contribute v=0 via predication
    for (; i < e; i += 4) {
        int  m = i + slot;
        bool p = (m < e);
        int  mm = p ? m : i;
        unsigned long long pr = __ldg(&ev[mm]);
        int2 q = *(int2*)&pr;
        float v = p ? __int_as_float(q.y) : 0.f;
        uint4 T = *(const uint4*)(gbase + (size_t)(unsigned)q.x * 128);
        unsigned long long vv = packff(v, v);
        acc0 = fma2(h2_to_f32x2(T.x), vv, acc0);
        acc1 = fma2(h2_to_f32x2(T.y), vv, acc1);
        acc2 = fma2(h2_to_f32x2(T.z), vv, acc2);
        acc3 = fma2(h2_to_f32x2(T.w), vv, acc3);
    }

    float r0, r1, r2, r3, r4, r5, r6, r7;
    unpack2(acc0, r0, r1);
    unpack2(acc1, r2, r3);
    unpack2(acc2, r4, r5);
    unpack2(acc3, r6, r7);

    // reduce the 4 slots
    r0 += __shfl_xor_sync(0xffffffffu, r0, 8);
    r1 += __shfl_xor_sync(0xffffffffu, r1, 8);
    r2 += __shfl_xor_sync(0xffffffffu, r2, 8);
    r3 += __shfl_xor_sync(0xffffffffu, r3, 8);
    r4 += __shfl_xor_sync(0xffffffffu, r4, 8);
    r5 += __shfl_xor_sync(0xffffffffu, r5, 8);
    r6 += __shfl_xor_sync(0xffffffffu, r6, 8);
    r7 += __shfl_xor_sync(0xffffffffu, r7, 8);
    r0 += __shfl_xor_sync(0xffffffffu, r0, 16);
    r1 += __shfl_xor_sync(0xffffffffu, r1, 16);
    r2 += __shfl_xor_sync(0xffffffffu, r2, 16);
    r3 += __shfl_xor_sync(0xffffffffu, r3, 16);
    r4 += __shfl_xor_sync(0xffffffffu, r4, 16);
    r5 += __shfl_xor_sync(0xffffffffu, r5, 16);
    r6 += __shfl_xor_sync(0xffffffffu, r6, 16);
    r7 += __shfl_xor_sync(0xffffffffu, r7, 16);

    if (lane < 8) {
        float4 b0 = ((const float4*)b)[lane * 2];
        float4 b1 = ((const float4*)b)[lane * 2 + 1];
        float4 o0 = make_float4(r0 + b0.x, r1 + b0.y, r2 + b0.z, r3 + b0.w);
        float4 o1 = make_float4(r4 + b1.x, r5 + b1.y, r6 + b1.z, r7 + b1.w);
        float4* op = (float4*)(out + (size_t)w * 64 + lane * 8);
        __stcs(&op[0], o0);
        __stcs(&op[1], o1);
    }
}

// ---------------------------------------------------------------------------
extern "C" void kernel_launch(void* const* d_in, const int* in_sizes, int n_in,
                              void* d_out, int out_size) {
    const float* feat     = (const float*)d_in[0];
    const int*   edge_row = (const int*)  d_in[1];
    const int*   edge_col = (const int*)  d_in[2];
    const float* edge_val = (const float*)d_in[3];
    const float* W        = (const float*)d_in[4];
    const float* b        = (const float*)d_in[5];
    float*       out      = (float*)d_out;

    __half* g;
    int*    row_start;
    unsigned long long* ev;
    cudaGetSymbolAddress((void**)&g, g_buf);
    cudaGetSymbolAddress((void**)&row_start, g_row_start);
    cudaGetSymbolAddress((void**)&ev, ev_buf);

    // 1) fused: rowptr scan + (col,val) pack + g = half(feat @ W^T)
    prep_kernel<<<NB_ROW + NB_PACK + NB_GEMM, 256>>>(edge_row, row_start,
                                                     edge_col, edge_val, ev,
                                                     feat, W, g);

    // 2) out = A @ g + b   (one warp per node, 16 edges/iter)
    int total_threads = N_NODES * 32;
    spmm_kernel<<<(total_threads + 255) / 256, 256>>>(row_start, ev, g, b, out);
}